// round 9
// baseline (speedup 1.0000x reference)
#include <cuda_runtime.h>
#include <cuda_fp16.h>

// Problem shape (fixed by the dataset): N=50000, E=800000, D=64.
#define MAXN 50000
#define MAXE 800000

// Scratch (allocation-free: __device__ globals)
__device__ int     g_is64;
__device__ int     g_deg[MAXN];
__device__ int     g_rowptr[MAXN + 1];
__device__ int     g_rank[MAXE];      // per-edge rank within its dst bucket
__device__ int     g_csrc[MAXE];
__device__ __half2 g_h2[MAXN * 32];   // h' = (x@W)*dis[row], fp16, col pairs

// Zero the degree array; thread 0 sniffs the edge_index dtype.
// int64 little-endian with values < 2^31 => odd 32-bit words are all 0.
__global__ void k_init(const int* __restrict__ ei32, int n) {
    int i = blockIdx.x * blockDim.x + threadIdx.x;
    if (i < n) g_deg[i] = 0;
    if (i == 0) {
        int zeros = 0;
        for (int j = 0; j < 64; j++)
            if (ei32[2 * j + 1] == 0) zeros++;
        g_is64 = (zeros >= 48) ? 1 : 0;
    }
}

__device__ __forceinline__ int edge_at(const void* ei, long long idx, int is64) {
    if (is64) return (int)((const long long*)ei)[idx];
    return ((const int*)ei)[idx];
}

// in-degree histogram on dst; the atomicAdd return IS the edge's rank within
// its bucket — persist it so the scatter pass needs no atomics at all.
__global__ void k_count(const void* __restrict__ ei, int e, int n) {
    int i0 = (blockIdx.x * blockDim.x + threadIdx.x) * 2;
    if (i0 >= e) return;
    int is64 = g_is64;
    if (!is64 && i0 + 2 <= e) {
        int2 d = *(const int2*)((const int*)ei + e + i0);
        int2 r = make_int2(0, 0);
        if (d.x >= 0 && d.x < n) r.x = atomicAdd(&g_deg[d.x], 1);
        if (d.y >= 0 && d.y < n) r.y = atomicAdd(&g_deg[d.y], 1);
        *(int2*)&g_rank[i0] = r;
    } else {
        for (int j = 0; j < 2 && i0 + j < e; j++) {
            int d = edge_at(ei, (long long)e + i0 + j, is64);
            int r = 0;
            if (d >= 0 && d < n) r = atomicAdd(&g_deg[d], 1);
            g_rank[i0 + j] = r;
        }
    }
}

// Single-block exclusive scan of g_deg -> g_rowptr, int4-vectorized.
__global__ void k_scan(int n, int e) {
    __shared__ int s[1024];
    const int t = threadIdx.x;
    const int seg = 52;                       // 1024*52 = 53248 >= 50000, 52%4==0
    int base = t * seg;
    int end = min(base + seg, n);

    int sum = 0;
    int j = base;
    for (; j + 4 <= end; j += 4) {
        int4 d = *(const int4*)&g_deg[j];
        sum += (d.x + d.y) + (d.z + d.w);
    }
    for (; j < end; j++) sum += g_deg[j];
    s[t] = sum;
    __syncthreads();

    for (int off = 1; off < 1024; off <<= 1) {
        int v = (t >= off) ? s[t - off] : 0;
        __syncthreads();
        s[t] += v;
        __syncthreads();
    }
    int run = s[t] - sum;                     // exclusive prefix of this segment

    j = base;
    for (; j + 4 <= end; j += 4) {
        int4 d = *(const int4*)&g_deg[j];
        int4 rp;
        rp.x = run; run += d.x;
        rp.y = run; run += d.y;
        rp.z = run; run += d.z;
        rp.w = run; run += d.w;
        *(int4*)&g_rowptr[j] = rp;
    }
    for (; j < end; j++) {
        g_rowptr[j] = run;
        run += g_deg[j];
    }
    if (t == 0) g_rowptr[n] = e;
}

// Atomic-free scatter: slot = rowptr[dst] + rank[edge]. Pure loads + one
// scattered STG per edge; fully independent chains (high MLP).
__global__ void k_scatter(const void* __restrict__ ei, int e, int n) {
    int i0 = (blockIdx.x * blockDim.x + threadIdx.x) * 2;
    if (i0 >= e) return;
    int is64 = g_is64;
    if (!is64 && i0 + 2 <= e) {
        int2 sr = *(const int2*)((const int*)ei + i0);
        int2 ds = *(const int2*)((const int*)ei + e + i0);
        int2 rk = *(const int2*)&g_rank[i0];
        if (ds.x >= 0 && ds.x < n && sr.x >= 0 && sr.x < n) {
            int pos = g_rowptr[ds.x] + rk.x;
            if (pos >= 0 && pos < e) g_csrc[pos] = sr.x;
        }
        if (ds.y >= 0 && ds.y < n && sr.y >= 0 && sr.y < n) {
            int pos = g_rowptr[ds.y] + rk.y;
            if (pos >= 0 && pos < e) g_csrc[pos] = sr.y;
        }
    } else {
        for (int j = 0; j < 2 && i0 + j < e; j++) {
            int srcn = edge_at(ei, i0 + j, is64);
            int dstn = edge_at(ei, (long long)e + i0 + j, is64);
            if (dstn >= 0 && dstn < n && srcn >= 0 && srcn < n) {
                int pos = g_rowptr[dstn] + g_rank[i0 + j];
                if (pos >= 0 && pos < e) g_csrc[pos] = srcn;
            }
        }
    }
}

// h' = (x @ W) * dis[row], stored fp16. 64 rows/block, 4x4 register tile.
__global__ __launch_bounds__(256) void k_gemm(const float* __restrict__ x,
                                              const float* __restrict__ W, int n) {
    __shared__ float xs[64 * 64];
    __shared__ float Ws[64 * 64];
    const int tid = threadIdx.x;
    const int row0 = blockIdx.x * 64;

    const float4* W4 = (const float4*)W;
    float4* Ws4 = (float4*)Ws;
    for (int i = tid; i < 1024; i += 256) Ws4[i] = W4[i];

    const float4* x4 = (const float4*)x;
    float4* xs4 = (float4*)xs;
    for (int i = tid; i < 1024; i += 256) {
        int r = i >> 4;                       // 16 float4 per row
        int gr = row0 + r;
        float4 v = make_float4(0.f, 0.f, 0.f, 0.f);
        if (gr < n) v = x4[gr * 16 + (i & 15)];
        xs4[i] = v;
    }
    __syncthreads();

    const int cx = tid & 15;                  // cols cx*4 .. cx*4+3
    const int cy = tid >> 4;                  // rows cy*4 .. cy*4+3
    float acc[4][4] = {};

#pragma unroll 8
    for (int k = 0; k < 64; k++) {
        float4 w = *(const float4*)&Ws[k * 64 + cx * 4];
        float x0 = xs[(cy * 4 + 0) * 64 + k];
        float x1 = xs[(cy * 4 + 1) * 64 + k];
        float x2 = xs[(cy * 4 + 2) * 64 + k];
        float x3 = xs[(cy * 4 + 3) * 64 + k];
        acc[0][0] = fmaf(x0, w.x, acc[0][0]); acc[0][1] = fmaf(x0, w.y, acc[0][1]);
        acc[0][2] = fmaf(x0, w.z, acc[0][2]); acc[0][3] = fmaf(x0, w.w, acc[0][3]);
        acc[1][0] = fmaf(x1, w.x, acc[1][0]); acc[1][1] = fmaf(x1, w.y, acc[1][1]);
        acc[1][2] = fmaf(x1, w.z, acc[1][2]); acc[1][3] = fmaf(x1, w.w, acc[1][3]);
        acc[2][0] = fmaf(x2, w.x, acc[2][0]); acc[2][1] = fmaf(x2, w.y, acc[2][1]);
        acc[2][2] = fmaf(x2, w.z, acc[2][2]); acc[2][3] = fmaf(x2, w.w, acc[2][3]);
        acc[3][0] = fmaf(x3, w.x, acc[3][0]); acc[3][1] = fmaf(x3, w.y, acc[3][1]);
        acc[3][2] = fmaf(x3, w.z, acc[3][2]); acc[3][3] = fmaf(x3, w.w, acc[3][3]);
    }

#pragma unroll
    for (int j = 0; j < 4; j++) {
        int gr = row0 + cy * 4 + j;
        if (gr < n) {
            int d = g_deg[gr];
            float dis = (d > 0) ? rsqrtf((float)d) : 0.f;
            __half2 p0 = __floats2half2_rn(acc[j][0] * dis, acc[j][1] * dis);
            __half2 p1 = __floats2half2_rn(acc[j][2] * dis, acc[j][3] * dis);
            __half2* dst = &g_h2[gr * 32 + cx * 2];
            dst[0] = p0;
            dst[1] = p1;
        }
    }
}

// One warp per destination node. Lane l owns columns 2l, 2l+1 = ONE half2
// (4B LDG per edge per lane; whole row = one 128B line). 8-edge unroll.
// out[w] = dis[w] * sum_{edges} h'[src] + b     (fp32 accumulation)
__global__ void k_agg(const float* __restrict__ b, float* __restrict__ out, int n) {
    int w = (blockIdx.x * blockDim.x + threadIdx.x) >> 5;
    int lane = threadIdx.x & 31;
    if (w >= n) return;

    int beg = g_rowptr[w];
    int end = g_rowptr[w + 1];
    float a0 = 0.f, a1 = 0.f;

    int i = beg;
    for (; i + 8 <= end; i += 8) {
        int s0 = g_csrc[i + 0], s1 = g_csrc[i + 1];
        int s2 = g_csrc[i + 2], s3 = g_csrc[i + 3];
        int s4 = g_csrc[i + 4], s5 = g_csrc[i + 5];
        int s6 = g_csrc[i + 6], s7 = g_csrc[i + 7];
        float2 v0 = __half22float2(g_h2[s0 * 32 + lane]);
        float2 v1 = __half22float2(g_h2[s1 * 32 + lane]);
        float2 v2 = __half22float2(g_h2[s2 * 32 + lane]);
        float2 v3 = __half22float2(g_h2[s3 * 32 + lane]);
        float2 v4 = __half22float2(g_h2[s4 * 32 + lane]);
        float2 v5 = __half22float2(g_h2[s5 * 32 + lane]);
        float2 v6 = __half22float2(g_h2[s6 * 32 + lane]);
        float2 v7 = __half22float2(g_h2[s7 * 32 + lane]);
        a0 += ((v0.x + v1.x) + (v2.x + v3.x)) + ((v4.x + v5.x) + (v6.x + v7.x));
        a1 += ((v0.y + v1.y) + (v2.y + v3.y)) + ((v4.y + v5.y) + (v6.y + v7.y));
    }
    for (; i < end; i++) {
        int s = g_csrc[i];
        float2 v = __half22float2(g_h2[s * 32 + lane]);
        a0 += v.x;
        a1 += v.y;
    }

    int d = end - beg;
    float dd = (d > 0) ? rsqrtf((float)d) : 0.f;
    const int c = lane * 2;
    float2 bb = *(const float2*)&b[c];
    float2 o;
    o.x = fmaf(a0, dd, bb.x);
    o.y = fmaf(a1, dd, bb.y);
    *(float2*)&out[w * 64 + c] = o;
}

extern "C" void kernel_launch(void* const* d_in, const int* in_sizes, int n_in,
                              void* d_out, int out_size) {
    // Identify inputs by element count (unique per input for this problem).
    const float* x  = nullptr;
    const void*  ei = nullptr;
    const float* W  = nullptr;
    const float* b  = nullptr;
    int n = MAXN, e = MAXE;

    for (int i = 0; i < n_in; i++) {
        int sz = in_sizes[i];
        if (sz == 3200000)      { x  = (const float*)d_in[i]; n = sz / 64; }
        else if (sz == 1600000) { ei = d_in[i]; e = sz / 2; }
        else if (sz == 4096)    { W  = (const float*)d_in[i]; }
        else if (sz == 64)      { b  = (const float*)d_in[i]; }
    }
    float* out = (float*)d_out;
    if (!x || !ei || !W || !b) return;

    int e2 = (e + 1) / 2;
    int eblocks = (e2 + 255) / 256;          // 2 edges/thread

    k_init   <<<(n + 255) / 256, 256>>>((const int*)ei, n);
    k_count  <<<eblocks, 256>>>(ei, e, n);
    k_scan   <<<1, 1024>>>(n, e);
    k_scatter<<<eblocks, 256>>>(ei, e, n);
    k_gemm   <<<(n + 63) / 64, 256>>>(x, W, n);
    k_agg    <<<(n * 32 + 255) / 256, 256>>>(b, out, n);
}

// round 10
// speedup vs baseline: 1.0511x; 1.0511x over previous
#include <cuda_runtime.h>
#include <cuda_fp16.h>

// Problem shape (fixed by the dataset): N=50000, E=800000, D=64.
#define MAXN 50000
#define MAXE 800000

// Scratch (allocation-free: __device__ globals)
__device__ int     g_is64;
__device__ int     g_deg[MAXN];
__device__ int     g_rowptr[MAXN + 1];
__device__ int     g_rank[MAXE];       // per-edge rank within its dst bucket
__device__ int     g_csrc[MAXE];
__device__ __half2 g_hraw2[MAXN * 32]; // x@W, fp16 col pairs
__device__ __half2 g_h2[MAXN * 32];    // (x@W)*dis[row], fp16 col pairs

// Zero the degree array; thread 0 sniffs the edge_index dtype.
// int64 little-endian with values < 2^31 => odd 32-bit words are all 0.
__global__ void k_init(const int* __restrict__ ei32, int n) {
    int i = blockIdx.x * blockDim.x + threadIdx.x;
    if (i < n) g_deg[i] = 0;
    if (i == 0) {
        int zeros = 0;
        for (int j = 0; j < 64; j++)
            if (ei32[2 * j + 1] == 0) zeros++;
        g_is64 = (zeros >= 48) ? 1 : 0;
    }
}

__device__ __forceinline__ int edge_at(const void* ei, long long idx, int is64) {
    if (is64) return (int)((const long long*)ei)[idx];
    return ((const int*)ei)[idx];
}

// in-degree histogram on dst; the atomicAdd return IS the edge's rank within
// its bucket — persist it so the scatter pass needs no atomics at all.
__global__ void k_count(const void* __restrict__ ei, int e, int n) {
    int i0 = (blockIdx.x * blockDim.x + threadIdx.x) * 2;
    if (i0 >= e) return;
    int is64 = g_is64;
    if (!is64 && i0 + 2 <= e) {
        int2 d = *(const int2*)((const int*)ei + e + i0);
        int2 r = make_int2(0, 0);
        if (d.x >= 0 && d.x < n) r.x = atomicAdd(&g_deg[d.x], 1);
        if (d.y >= 0 && d.y < n) r.y = atomicAdd(&g_deg[d.y], 1);
        *(int2*)&g_rank[i0] = r;
    } else {
        for (int j = 0; j < 2 && i0 + j < e; j++) {
            int d = edge_at(ei, (long long)e + i0 + j, is64);
            int r = 0;
            if (d >= 0 && d < n) r = atomicAdd(&g_deg[d], 1);
            g_rank[i0 + j] = r;
        }
    }
}

// Single-block exclusive scan of g_deg -> g_rowptr, int4-vectorized.
__global__ void k_scan(int n, int e) {
    __shared__ int s[1024];
    const int t = threadIdx.x;
    const int seg = 52;                       // 1024*52 = 53248 >= 50000, 52%4==0
    int base = t * seg;
    int end = min(base + seg, n);

    int sum = 0;
    int j = base;
    for (; j + 4 <= end; j += 4) {
        int4 d = *(const int4*)&g_deg[j];
        sum += (d.x + d.y) + (d.z + d.w);
    }
    for (; j < end; j++) sum += g_deg[j];
    s[t] = sum;
    __syncthreads();

    for (int off = 1; off < 1024; off <<= 1) {
        int v = (t >= off) ? s[t - off] : 0;
        __syncthreads();
        s[t] += v;
        __syncthreads();
    }
    int run = s[t] - sum;                     // exclusive prefix of this segment

    j = base;
    for (; j + 4 <= end; j += 4) {
        int4 d = *(const int4*)&g_deg[j];
        int4 rp;
        rp.x = run; run += d.x;
        rp.y = run; run += d.y;
        rp.z = run; run += d.z;
        rp.w = run; run += d.w;
        *(int4*)&g_rowptr[j] = rp;
    }
    for (; j < end; j++) {
        g_rowptr[j] = run;
        run += g_deg[j];
    }
    if (t == 0) g_rowptr[n] = e;
}

// Atomic-free scatter: slot = rowptr[dst] + rank[edge]. Pure loads + one
// scattered STG per edge; fully independent chains (high MLP).
__global__ void k_scatter(const void* __restrict__ ei, int e, int n) {
    int i0 = (blockIdx.x * blockDim.x + threadIdx.x) * 2;
    if (i0 >= e) return;
    int is64 = g_is64;
    if (!is64 && i0 + 2 <= e) {
        int2 sr = *(const int2*)((const int*)ei + i0);
        int2 ds = *(const int2*)((const int*)ei + e + i0);
        int2 rk = *(const int2*)&g_rank[i0];
        if (ds.x >= 0 && ds.x < n && sr.x >= 0 && sr.x < n) {
            int pos = g_rowptr[ds.x] + rk.x;
            if (pos >= 0 && pos < e) g_csrc[pos] = sr.x;
        }
        if (ds.y >= 0 && ds.y < n && sr.y >= 0 && sr.y < n) {
            int pos = g_rowptr[ds.y] + rk.y;
            if (pos >= 0 && pos < e) g_csrc[pos] = sr.y;
        }
    } else {
        for (int j = 0; j < 2 && i0 + j < e; j++) {
            int srcn = edge_at(ei, i0 + j, is64);
            int dstn = edge_at(ei, (long long)e + i0 + j, is64);
            if (dstn >= 0 && dstn < n && srcn >= 0 && srcn < n) {
                int pos = g_rowptr[dstn] + g_rank[i0 + j];
                if (pos >= 0 && pos < e) g_csrc[pos] = srcn;
            }
        }
    }
}

// h_raw = x @ W (fp16). NO dependence on the edge pipeline — runs on the
// side stream, overlapped with init/count. 64 rows/block, 4x4 register tile.
__global__ __launch_bounds__(256) void k_gemm_raw(const float* __restrict__ x,
                                                  const float* __restrict__ W, int n) {
    __shared__ float xs[64 * 64];
    __shared__ float Ws[64 * 64];
    const int tid = threadIdx.x;
    const int row0 = blockIdx.x * 64;

    const float4* W4 = (const float4*)W;
    float4* Ws4 = (float4*)Ws;
    for (int i = tid; i < 1024; i += 256) Ws4[i] = W4[i];

    const float4* x4 = (const float4*)x;
    float4* xs4 = (float4*)xs;
    for (int i = tid; i < 1024; i += 256) {
        int r = i >> 4;                       // 16 float4 per row
        int gr = row0 + r;
        float4 v = make_float4(0.f, 0.f, 0.f, 0.f);
        if (gr < n) v = x4[gr * 16 + (i & 15)];
        xs4[i] = v;
    }
    __syncthreads();

    const int cx = tid & 15;                  // cols cx*4 .. cx*4+3
    const int cy = tid >> 4;                  // rows cy*4 .. cy*4+3
    float acc[4][4] = {};

#pragma unroll 8
    for (int k = 0; k < 64; k++) {
        float4 w = *(const float4*)&Ws[k * 64 + cx * 4];
        float x0 = xs[(cy * 4 + 0) * 64 + k];
        float x1 = xs[(cy * 4 + 1) * 64 + k];
        float x2 = xs[(cy * 4 + 2) * 64 + k];
        float x3 = xs[(cy * 4 + 3) * 64 + k];
        acc[0][0] = fmaf(x0, w.x, acc[0][0]); acc[0][1] = fmaf(x0, w.y, acc[0][1]);
        acc[0][2] = fmaf(x0, w.z, acc[0][2]); acc[0][3] = fmaf(x0, w.w, acc[0][3]);
        acc[1][0] = fmaf(x1, w.x, acc[1][0]); acc[1][1] = fmaf(x1, w.y, acc[1][1]);
        acc[1][2] = fmaf(x1, w.z, acc[1][2]); acc[1][3] = fmaf(x1, w.w, acc[1][3]);
        acc[2][0] = fmaf(x2, w.x, acc[2][0]); acc[2][1] = fmaf(x2, w.y, acc[2][1]);
        acc[2][2] = fmaf(x2, w.z, acc[2][2]); acc[2][3] = fmaf(x2, w.w, acc[2][3]);
        acc[3][0] = fmaf(x3, w.x, acc[3][0]); acc[3][1] = fmaf(x3, w.y, acc[3][1]);
        acc[3][2] = fmaf(x3, w.z, acc[3][2]); acc[3][3] = fmaf(x3, w.w, acc[3][3]);
    }

#pragma unroll
    for (int j = 0; j < 4; j++) {
        int gr = row0 + cy * 4 + j;
        if (gr < n) {
            __half2 p0 = __floats2half2_rn(acc[j][0], acc[j][1]);
            __half2 p1 = __floats2half2_rn(acc[j][2], acc[j][3]);
            __half2* dst = &g_hraw2[gr * 32 + cx * 2];
            dst[0] = p0;
            dst[1] = p1;
        }
    }
}

// h' = h_raw * dis[row].  Needs only g_deg (count) + g_hraw2 (gemm_raw);
// runs on the side stream, overlapped with scan/scatter.
__global__ void k_scale(int n) {
    int i = blockIdx.x * blockDim.x + threadIdx.x;   // one half2 per thread
    if (i >= n * 32) return;
    int row = i >> 5;
    int d = g_deg[row];
    float dis = (d > 0) ? rsqrtf((float)d) : 0.f;
    float2 v = __half22float2(g_hraw2[i]);
    g_h2[i] = __floats2half2_rn(v.x * dis, v.y * dis);
}

// One warp per destination node. Lane l owns columns 2l, 2l+1 = ONE half2
// (4B LDG per edge per lane). 8-edge unroll.
// out[w] = dis[w] * sum_{edges} h'[src] + b     (fp32 accumulation)
__global__ void k_agg(const float* __restrict__ b, float* __restrict__ out, int n) {
    int w = (blockIdx.x * blockDim.x + threadIdx.x) >> 5;
    int lane = threadIdx.x & 31;
    if (w >= n) return;

    int beg = g_rowptr[w];
    int end = g_rowptr[w + 1];
    float a0 = 0.f, a1 = 0.f;

    int i = beg;
    for (; i + 8 <= end; i += 8) {
        int s0 = g_csrc[i + 0], s1 = g_csrc[i + 1];
        int s2 = g_csrc[i + 2], s3 = g_csrc[i + 3];
        int s4 = g_csrc[i + 4], s5 = g_csrc[i + 5];
        int s6 = g_csrc[i + 6], s7 = g_csrc[i + 7];
        float2 v0 = __half22float2(g_h2[s0 * 32 + lane]);
        float2 v1 = __half22float2(g_h2[s1 * 32 + lane]);
        float2 v2 = __half22float2(g_h2[s2 * 32 + lane]);
        float2 v3 = __half22float2(g_h2[s3 * 32 + lane]);
        float2 v4 = __half22float2(g_h2[s4 * 32 + lane]);
        float2 v5 = __half22float2(g_h2[s5 * 32 + lane]);
        float2 v6 = __half22float2(g_h2[s6 * 32 + lane]);
        float2 v7 = __half22float2(g_h2[s7 * 32 + lane]);
        a0 += ((v0.x + v1.x) + (v2.x + v3.x)) + ((v4.x + v5.x) + (v6.x + v7.x));
        a1 += ((v0.y + v1.y) + (v2.y + v3.y)) + ((v4.y + v5.y) + (v6.y + v7.y));
    }
    for (; i < end; i++) {
        int s = g_csrc[i];
        float2 v = __half22float2(g_h2[s * 32 + lane]);
        a0 += v.x;
        a1 += v.y;
    }

    int d = end - beg;
    float dd = (d > 0) ? rsqrtf((float)d) : 0.f;
    const int c = lane * 2;
    float2 bb = *(const float2*)&b[c];
    float2 o;
    o.x = fmaf(a0, dd, bb.x);
    o.y = fmaf(a1, dd, bb.y);
    *(float2*)&out[w * 64 + c] = o;
}

extern "C" void kernel_launch(void* const* d_in, const int* in_sizes, int n_in,
                              void* d_out, int out_size) {
    // Identify inputs by element count (unique per input for this problem).
    const float* x  = nullptr;
    const void*  ei = nullptr;
    const float* W  = nullptr;
    const float* b  = nullptr;
    int n = MAXN, e = MAXE;

    for (int i = 0; i < n_in; i++) {
        int sz = in_sizes[i];
        if (sz == 3200000)      { x  = (const float*)d_in[i]; n = sz / 64; }
        else if (sz == 1600000) { ei = d_in[i]; e = sz / 2; }
        else if (sz == 4096)    { W  = (const float*)d_in[i]; }
        else if (sz == 64)      { b  = (const float*)d_in[i]; }
    }
    float* out = (float*)d_out;
    if (!x || !ei || !W || !b) return;

    // Lazy one-time stream/event creation (happens on the uncaptured
    // correctness call; reused as graph fork/join edges during capture).
    static cudaStream_t sB = nullptr;
    static cudaEvent_t evFork = nullptr, evCnt = nullptr, evB = nullptr;
    if (!sB) {
        cudaStreamCreateWithFlags(&sB, cudaStreamNonBlocking);
        cudaEventCreateWithFlags(&evFork, cudaEventDisableTiming);
        cudaEventCreateWithFlags(&evCnt,  cudaEventDisableTiming);
        cudaEventCreateWithFlags(&evB,    cudaEventDisableTiming);
    }

    int e2 = (e + 1) / 2;
    int eblocks = (e2 + 255) / 256;          // 2 edges/thread

    // Fork: side stream B does gemm_raw (independent) then scale (needs count).
    cudaEventRecord(evFork, 0);
    cudaStreamWaitEvent(sB, evFork, 0);
    k_gemm_raw<<<(n + 63) / 64, 256, 0, sB>>>(x, W, n);

    // Stream A (default): edge pipeline.
    k_init <<<(n + 255) / 256, 256>>>((const int*)ei, n);
    k_count<<<eblocks, 256>>>(ei, e, n);
    cudaEventRecord(evCnt, 0);

    cudaStreamWaitEvent(sB, evCnt, 0);
    k_scale<<<(n * 32 + 255) / 256, 256, 0, sB>>>(n);   // overlaps scan+scatter
    cudaEventRecord(evB, sB);

    k_scan   <<<1, 1024>>>(n, e);
    k_scatter<<<eblocks, 256>>>(ei, e, n);

    // Join: agg needs scatter (stream A) + scale (stream B).
    cudaStreamWaitEvent(0, evB, 0);
    k_agg<<<(n * 32 + 255) / 256, 256>>>(b, out, n);
}